// round 1
// baseline (speedup 1.0000x reference)
#include <cuda_runtime.h>
#include <cstdint>
#include <cstddef>

// ---------------------------------------------------------------------------
// FeedForward: 3x (irrep-linear [+gate]) + bypass + batch-norm, N=100000
// Layout notes:
//   features: (N, 640)   = [256 scalars | 128 vectors * 3 (i,d interleaved)]
//   h_pre:    (N, 1536)  = [768 (s+g) | 256 vec-out * 3]
//   h_gated:  (N, 1280)  = [512 silu(s) | 256 vec * 3 gated]
//   out:      (N, 640)   = [256 scalars | 128 vec * 3]
// ---------------------------------------------------------------------------

#define MROWS 100000

// Scratch (static __device__ — allocation inside kernel_launch is forbidden)
__device__ float g_pre[(size_t)MROWS * 1536]; // 614 MB  (h1_pre, then h2_pre)
__device__ float g_h[(size_t)MROWS * 1280];   // 512 MB  (h1, then h2)
#define NPART 512
__device__ float g_psum[NPART * 256];
__device__ float g_psq[NPART * 640];
__device__ float g_scale[640];
__device__ float g_shift[640];

// ---------------------------------------------------------------------------
// Generic tiled fp32 GEMM:
//   C[m, cOff + d + n*cStride] (+)= scale * sum_k A[m, aOff + d + k*aStride] * B[k*ldb + bn + n]
// d = blockIdx.z handles the 3 vector components (aStride/cStride = 3).
// ---------------------------------------------------------------------------
#define BM 128
#define BN 64
#define BK 16

__global__ __launch_bounds__(256) void gemm_kernel(
    const float* __restrict__ A, int lda, int aOff, int aStride,
    const float* __restrict__ B, int ldb,
    float* __restrict__ C, int ldc, int cOff, int cStride,
    int M, int K, float scale, int accumulate)
{
    __shared__ float As[BK][BM + 1];
    __shared__ float Bs[BK][BN];

    const int bm = blockIdx.y * BM;
    const int bn = blockIdx.x * BN;
    const int d  = blockIdx.z;
    const float* Ab = A + aOff + d;
    float*       Cb = C + cOff + d;

    const int tid = threadIdx.x;
    const int tx = tid & 15;   // output col group (4 cols each)
    const int ty = tid >> 4;   // output row group (8 rows each)

    float acc[8][4];
#pragma unroll
    for (int i = 0; i < 8; i++)
#pragma unroll
        for (int j = 0; j < 4; j++) acc[i][j] = 0.f;

    const int ak  = tid & 15;   // A: k index
    const int am0 = tid >> 4;   // A: m base (stride 16, 8 iters)
    const int bnl = tid & 63;   // B: n index
    const int bk0 = tid >> 6;   // B: k base (stride 4, 4 iters)

    for (int k0 = 0; k0 < K; k0 += BK) {
#pragma unroll
        for (int i = 0; i < 8; i++) {
            int m = am0 + i * 16;
            int gm = bm + m;
            float v = 0.f;
            if (gm < M)
                v = Ab[(size_t)gm * lda + (size_t)(k0 + ak) * aStride];
            As[ak][m] = v;
        }
#pragma unroll
        for (int i = 0; i < 4; i++) {
            int k = bk0 + i * 4;
            Bs[k][bnl] = B[(size_t)(k0 + k) * ldb + bn + bnl];
        }
        __syncthreads();
#pragma unroll
        for (int k = 0; k < BK; k++) {
            float a[8], b[4];
#pragma unroll
            for (int i = 0; i < 8; i++) a[i] = As[k][ty * 8 + i];
#pragma unroll
            for (int j = 0; j < 4; j++) b[j] = Bs[k][tx * 4 + j];
#pragma unroll
            for (int i = 0; i < 8; i++)
#pragma unroll
                for (int j = 0; j < 4; j++) acc[i][j] += a[i] * b[j];
        }
        __syncthreads();
    }

#pragma unroll
    for (int i = 0; i < 8; i++) {
        int gm = bm + ty * 8 + i;
        if (gm >= M) continue;
#pragma unroll
        for (int j = 0; j < 4; j++) {
            int gn = bn + tx * 4 + j;
            size_t idx = (size_t)gm * ldc + (size_t)gn * cStride;
            float v = acc[i][j] * scale;
            if (accumulate) v += Cb[idx];
            Cb[idx] = v;
        }
    }
}

// ---------------------------------------------------------------------------
// Gate: (N,1536) -> (N,1280)
//   out[:,0:512)          = silu(pre[:,0:512))
//   out[:,512 + 3o + d]   = pre[:,768 + 3o + d] * sigmoid(pre[:,512 + o])
// ---------------------------------------------------------------------------
__global__ void gate_kernel(const float* __restrict__ pre, float* __restrict__ out, int M)
{
    size_t idx = (size_t)blockIdx.x * blockDim.x + threadIdx.x;
    size_t total = (size_t)M * 1280;
    if (idx >= total) return;
    int c = (int)(idx % 1280);
    size_t r = idx / 1280;
    const float* prow = pre + r * 1536;
    float v;
    if (c < 512) {
        float s = prow[c];
        v = s / (1.f + __expf(-s));
    } else {
        int c2 = c - 512;
        int o = c2 / 3;
        float g = 1.f / (1.f + __expf(-prow[512 + o]));
        v = prow[768 + c2] * g;
    }
    out[idx] = v;
}

// ---------------------------------------------------------------------------
// Batch-norm: deterministic two-stage reduction, then per-column scale/shift.
// ---------------------------------------------------------------------------
__global__ void bn_partial_kernel(const float* __restrict__ out,
                                  float* __restrict__ psum, float* __restrict__ psq, int M)
{
    int c = threadIdx.x; // 0..639
    float s = 0.f, sq = 0.f;
    for (int r = blockIdx.x; r < M; r += gridDim.x) {
        float x = out[(size_t)r * 640 + c];
        s  += x;
        sq += x * x;
    }
    psq[blockIdx.x * 640 + c] = sq;
    if (c < 256) psum[blockIdx.x * 256 + c] = s;
}

__global__ void bn_final_kernel(const float* __restrict__ psum, const float* __restrict__ psq,
                                const float* __restrict__ w, const float* __restrict__ b,
                                float* __restrict__ scale, float* __restrict__ shift, int M)
{
    __shared__ float ssq[640];
    __shared__ float ssum[256];
    int c = threadIdx.x;
    float sq = 0.f;
    for (int p = 0; p < NPART; p++) sq += psq[p * 640 + c];
    ssq[c] = sq;
    if (c < 256) {
        float s = 0.f;
        for (int p = 0; p < NPART; p++) s += psum[p * 256 + c];
        ssum[c] = s;
    }
    __syncthreads();
    float invN = 1.f / (float)M;
    if (c < 256) {
        float m   = ssum[c] * invN;
        float var = ssq[c] * invN - m * m;
        float inv = rsqrtf(var + 1e-5f);
        float sc  = inv * w[c];
        scale[c] = sc;
        shift[c] = b[c] - m * sc;
    } else if (c < 256 + 128) {
        int ch = c - 256;
        float t = ssq[256 + 3 * ch] + ssq[256 + 3 * ch + 1] + ssq[256 + 3 * ch + 2];
        float mean = t * invN * (1.f / 3.f);
        float inv = rsqrtf(mean + 1e-5f);
        float sc  = inv * w[256 + ch];
#pragma unroll
        for (int d2 = 0; d2 < 3; d2++) {
            scale[256 + 3 * ch + d2] = sc;
            shift[256 + 3 * ch + d2] = 0.f;
        }
    }
}

__global__ void bn_apply_kernel(float* __restrict__ out,
                                const float* __restrict__ scale,
                                const float* __restrict__ shift, int M)
{
    size_t idx = (size_t)blockIdx.x * blockDim.x + threadIdx.x;
    size_t total = (size_t)M * 640;
    if (idx >= total) return;
    int c = (int)(idx % 640);
    out[idx] = out[idx] * __ldg(&scale[c]) + __ldg(&shift[c]);
}

// ---------------------------------------------------------------------------
extern "C" void kernel_launch(void* const* d_in, const int* in_sizes, int n_in,
                              void* d_out, int out_size)
{
    const float* features = (const float*)d_in[0];
    const float* W10 = (const float*)d_in[1];   // (256, 768)
    const float* W11 = (const float*)d_in[2];   // (128, 256)
    const float* W20 = (const float*)d_in[3];   // (512, 768)
    const float* W21 = (const float*)d_in[4];   // (256, 256)
    const float* W30 = (const float*)d_in[5];   // (512, 256)
    const float* W31 = (const float*)d_in[6];   // (256, 128)
    const float* B0  = (const float*)d_in[7];   // (256, 256)
    const float* B1  = (const float*)d_in[8];   // (128, 128)
    const float* bw  = (const float*)d_in[9];   // (384,)
    const float* bb  = (const float*)d_in[10];  // (256,)
    float* out = (float*)d_out;

    float *pre, *h, *psum, *psq, *sc, *sh;
    cudaGetSymbolAddress((void**)&pre,  g_pre);
    cudaGetSymbolAddress((void**)&h,    g_h);
    cudaGetSymbolAddress((void**)&psum, g_psum);
    cudaGetSymbolAddress((void**)&psq,  g_psq);
    cudaGetSymbolAddress((void**)&sc,   g_scale);
    cudaGetSymbolAddress((void**)&sh,   g_shift);

    const int M = MROWS;
    const float s256 = 0.0625f;                  // 1/sqrt(256)
    const float s128 = 0.08838834764831845f;     // 1/sqrt(128)
    const float s512 = 0.04419417382415922f;     // 1/sqrt(512)
    const int gy = (M + BM - 1) / BM;
    dim3 blk(256);

    // ---- layer 1: features -> h1_pre (1536) ----
    gemm_kernel<<<dim3(768 / BN, gy, 1), blk>>>(features, 640, 0,   1, W10, 768, pre, 1536, 0,   1, M, 256, s256, 0);
    gemm_kernel<<<dim3(256 / BN, gy, 3), blk>>>(features, 640, 256, 3, W11, 256, pre, 1536, 768, 3, M, 128, s128, 0);
    {
        size_t total = (size_t)M * 1280;
        gate_kernel<<<(unsigned)((total + 255) / 256), 256>>>(pre, h, M);
    }
    // ---- layer 2: h1 -> h2_pre (1536) ----
    gemm_kernel<<<dim3(768 / BN, gy, 1), blk>>>(h, 1280, 0,   1, W20, 768, pre, 1536, 0,   1, M, 512, s512, 0);
    gemm_kernel<<<dim3(256 / BN, gy, 3), blk>>>(h, 1280, 512, 3, W21, 256, pre, 1536, 768, 3, M, 256, s256, 0);
    {
        size_t total = (size_t)M * 1280;
        gate_kernel<<<(unsigned)((total + 255) / 256), 256>>>(pre, h, M);
    }
    // ---- layer 3 + bypass -> out (640) ----
    gemm_kernel<<<dim3(256 / BN, gy, 1), blk>>>(h, 1280, 0,   1, W30, 256, out, 640, 0,   1, M, 512, s512, 0);
    gemm_kernel<<<dim3(128 / BN, gy, 3), blk>>>(h, 1280, 512, 3, W31, 128, out, 640, 256, 3, M, 256, s256, 0);
    gemm_kernel<<<dim3(256 / BN, gy, 1), blk>>>(features, 640, 0,   1, B0, 256, out, 640, 0,   1, M, 256, s256, 1);
    gemm_kernel<<<dim3(128 / BN, gy, 3), blk>>>(features, 640, 256, 3, B1, 128, out, 640, 256, 3, M, 128, s128, 1);

    // ---- batch norm ----
    bn_partial_kernel<<<NPART, 640>>>(out, psum, psq, M);
    bn_final_kernel<<<1, 640>>>(psum, psq, bw, bb, sc, sh, M);
    {
        size_t total = (size_t)M * 640;
        bn_apply_kernel<<<(unsigned)((total + 255) / 256), 256>>>(out, sc, sh, M);
    }
}

// round 3
// speedup vs baseline: 1.6246x; 1.6246x over previous
#include <cuda_runtime.h>
#include <cuda_bf16.h>
#include <cstdint>
#include <cstddef>

// ===========================================================================
// FeedForward via warp-level HMMA (mma.sync bf16, fp32 accum), split-precision
// bf16x3: C = Ah*Bh + Ah*Bl + Al*Bh  (K' = 3*BK concatenation trick)
//   features: (N, 640)  = [256 scalars | 128 vec * 3]
//   h_pre:    (N, 1536) = [768 s+g | 256 vec * 3]
//   h_gated:  (N, 1280) = [512 s | 256 vec * 3]
// ===========================================================================

#define MROWS 100000

// ------------------------------- scratch -----------------------------------
__device__ float g_pre[(size_t)MROWS * 1536];
__device__ float g_h[(size_t)MROWS * 1280];
#define NPART 512
__device__ float g_psum[NPART * 256];
__device__ float g_psq[NPART * 640];
__device__ float g_scale[640];
__device__ float g_shift[640];
#define WTOT 933888
__device__ __align__(256) __nv_bfloat16 g_wbuf[2 * WTOT];

// --------------------------- helpers ---------------------------------------
__device__ __forceinline__ uint32_t smem_to_u32(const void* p) {
    uint32_t a;
    asm("{ .reg .u64 t; cvta.to.shared.u64 t, %1; cvt.u32.u64 %0, t; }" : "=r"(a) : "l"(p));
    return a;
}
__device__ __forceinline__ void ldm4(uint32_t& r0, uint32_t& r1, uint32_t& r2, uint32_t& r3,
                                     uint32_t addr) {
    asm volatile("ldmatrix.sync.aligned.m8n8.x4.shared.b16 {%0,%1,%2,%3}, [%4];"
                 : "=r"(r0), "=r"(r1), "=r"(r2), "=r"(r3) : "r"(addr));
}
__device__ __forceinline__ void mma16816(float* c, const uint32_t* a, const uint32_t* b) {
    asm volatile(
        "mma.sync.aligned.m16n8k16.row.col.f32.bf16.bf16.f32 "
        "{%0,%1,%2,%3}, {%4,%5,%6,%7}, {%8,%9}, {%0,%1,%2,%3};"
        : "+f"(c[0]), "+f"(c[1]), "+f"(c[2]), "+f"(c[3])
        : "r"(a[0]), "r"(a[1]), "r"(a[2]), "r"(a[3]), "r"(b[0]), "r"(b[1]));
}

// ---------------------------------------------------------------------------
// Weight prep: W[K,N] fp32 -> hi/lo bf16 [N,K] K-major, scale folded in.
// ---------------------------------------------------------------------------
__global__ void conv_w_kernel(const float* __restrict__ W, int K, int N, float scale,
                              __nv_bfloat16* __restrict__ hi, __nv_bfloat16* __restrict__ lo) {
    int idx = blockIdx.x * blockDim.x + threadIdx.x;
    if (idx >= N * K) return;
    int n = idx / K, k = idx % K;
    float v = W[k * N + n] * scale;
    __nv_bfloat16 h = __float2bfloat16(v);
    hi[idx] = h;
    lo[idx] = __float2bfloat16(v - __bfloat162float(h));
}

// ---------------------------------------------------------------------------
// HMMA GEMM: C[m, cOff+z + n*cStride] (+)= sum_k A[m, aOff+z + k*aStride] * W[k,n]
// Block tile 128x128, BK=32 (K'=96 in smem). 8 warps (4x2), warp tile 32x64.
// ---------------------------------------------------------------------------
#define SA 104   // smem row stride in bf16 (208 B, conflict-free for ldmatrix)
#define ATILE (128 * SA)          // elements
#define SMEM_BYTES (2 * ATILE * 2)

__global__ __launch_bounds__(256) void tc_gemm(
    const float* __restrict__ A, int lda, int aOff, int aStride,
    const __nv_bfloat16* __restrict__ Bh, const __nv_bfloat16* __restrict__ Bl,
    float* __restrict__ C, int ldc, int cOff, int cStride,
    int M, int K, int accumulate)
{
    extern __shared__ __nv_bfloat16 smem[];
    __nv_bfloat16* As = smem;           // [128][SA], cols 0..95 used
    __nv_bfloat16* Bs = smem + ATILE;   // [128][SA]
    const uint32_t sA = smem_to_u32(As);
    const uint32_t sB = smem_to_u32(Bs);

    const int tid = threadIdx.x;
    const int wid = tid >> 5;
    const int lane = tid & 31;
    const int warp_m = wid & 3;         // 0..3 -> m offset *32
    const int warp_n = wid >> 2;        // 0..1 -> n offset *64
    const int bm = blockIdx.y * 128;
    const int bn = blockIdx.x * 128;
    const int z = blockIdx.z;
    const int aOffE = aOff + z;
    const int cOffE = cOff + z;

    // ldmatrix address components (quad-based row/k selection)
    const int quad = lane >> 3;
    const int rsel = (lane & 7) + ((quad & 1) << 3);
    const int ksel = (quad >> 1) << 3;   // 0 or 8 (bf16 cols)
    const uint32_t aAddr0 = sA + (uint32_t)((warp_m * 32 + rsel) * SA + ksel) * 2;
    const uint32_t aAddr1 = aAddr0 + 16 * SA * 2;
    const uint32_t bAddr0 = sB + (uint32_t)((warp_n * 64 + rsel) * SA + ksel) * 2;

    float acc[2][8][4];
#pragma unroll
    for (int mi = 0; mi < 2; mi++)
#pragma unroll
        for (int nj = 0; nj < 8; nj++)
#pragma unroll
            for (int r = 0; r < 4; r++) acc[mi][nj][r] = 0.f;

    const int nkt = K / 32;
    for (int kt = 0; kt < nkt; kt++) {
        const int k0 = kt * 32;
        __syncthreads();   // protect smem reuse from previous iter's ldmatrix
        // ---- A tile: 128 rows x 32 fp32 -> hi (cols 0-31 & 32-63), lo (64-95)
        if (aStride == 1) {
#pragma unroll
            for (int i = 0; i < 4; i++) {
                int t = tid + i * 256;          // 1024 float4 slots
                int row = t >> 3, c4 = t & 7;   // col = c4*4
                int gm = bm + row;
                float4 v = make_float4(0.f, 0.f, 0.f, 0.f);
                if (gm < M)
                    v = *(const float4*)&A[(size_t)gm * lda + aOffE + k0 + c4 * 4];
                __nv_bfloat162 h01 = __floats2bfloat162_rn(v.x, v.y);
                __nv_bfloat162 h23 = __floats2bfloat162_rn(v.z, v.w);
                float2 hf01 = __bfloat1622float2(h01);
                float2 hf23 = __bfloat1622float2(h23);
                __nv_bfloat162 l01 = __floats2bfloat162_rn(v.x - hf01.x, v.y - hf01.y);
                __nv_bfloat162 l23 = __floats2bfloat162_rn(v.z - hf23.x, v.w - hf23.y);
                uint2 hv = make_uint2(*(uint32_t*)&h01, *(uint32_t*)&h23);
                uint2 lv = make_uint2(*(uint32_t*)&l01, *(uint32_t*)&l23);
                __nv_bfloat16* rp = As + row * SA + c4 * 4;
                *(uint2*)(rp)       = hv;   // Ah
                *(uint2*)(rp + 32)  = hv;   // Ah (dup)
                *(uint2*)(rp + 64)  = lv;   // Al
            }
        } else {
#pragma unroll
            for (int i = 0; i < 16; i++) {
                int t = tid + i * 256;          // 4096 elements
                int row = t >> 5, col = t & 31;
                int gm = bm + row;
                float v = 0.f;
                if (gm < M)
                    v = A[(size_t)gm * lda + aOffE + (size_t)(k0 + col) * 3];
                __nv_bfloat16 h = __float2bfloat16(v);
                __nv_bfloat16 l = __float2bfloat16(v - __bfloat162float(h));
                __nv_bfloat16* rp = As + row * SA + col;
                rp[0]  = h;
                rp[32] = h;
                rp[64] = l;
            }
        }
        // ---- B tile: 128 n-rows x 32 k bf16: Bh -> cols 0-31 & 64-95, Bl -> 32-63
#pragma unroll
        for (int i = 0; i < 2; i++) {
            int t = tid + i * 256;              // 512 uint4 slots
            int n = t >> 2, c8 = t & 3;         // col = c8*8
            size_t base = (size_t)(bn + n) * K + k0 + c8 * 8;
            uint4 vh = *(const uint4*)&Bh[base];
            uint4 vl = *(const uint4*)&Bl[base];
            __nv_bfloat16* rp = Bs + n * SA + c8 * 8;
            *(uint4*)(rp)      = vh;   // Bh
            *(uint4*)(rp + 32) = vl;   // Bl
            *(uint4*)(rp + 64) = vh;   // Bh (dup)
        }
        __syncthreads();

        // ---- compute: 6 k16 steps over K'=96
#pragma unroll
        for (int ks = 0; ks < 6; ks++) {
            uint32_t af0[4], af1[4];
            ldm4(af0[0], af0[1], af0[2], af0[3], aAddr0 + ks * 32);
            ldm4(af1[0], af1[1], af1[2], af1[3], aAddr1 + ks * 32);
            uint32_t bf[8][2];
#pragma unroll
            for (int j2 = 0; j2 < 4; j2++) {
                uint32_t r0, r1, r2, r3;
                ldm4(r0, r1, r2, r3, bAddr0 + (uint32_t)(j2 * 16 * SA) * 2 + ks * 32);
                bf[2 * j2][0] = r0; bf[2 * j2 + 1][0] = r1;
                bf[2 * j2][1] = r2; bf[2 * j2 + 1][1] = r3;
            }
#pragma unroll
            for (int mi = 0; mi < 2; mi++)
#pragma unroll
                for (int nj = 0; nj < 8; nj++)
                    mma16816(acc[mi][nj], mi ? af1 : af0, bf[nj]);
        }
    }

    // ---- epilogue ----
    const int tq = lane >> 2;       // 0..7 (row within 8)
    const int tr = lane & 3;        // col pair
#pragma unroll
    for (int mi = 0; mi < 2; mi++) {
#pragma unroll
        for (int half = 0; half < 2; half++) {
            int gm = bm + warp_m * 32 + mi * 16 + tq + half * 8;
            if (gm >= M) continue;
            if (cStride == 1) {
                float* Crow = C + (size_t)gm * ldc + cOffE + bn + warp_n * 64;
#pragma unroll
                for (int nj = 0; nj < 8; nj++) {
                    int cn = nj * 8 + tr * 2;
                    float2 v = make_float2(acc[mi][nj][half * 2], acc[mi][nj][half * 2 + 1]);
                    if (accumulate) {
                        float2 o = *(float2*)&Crow[cn];
                        v.x += o.x; v.y += o.y;
                    }
                    *(float2*)&Crow[cn] = v;
                }
            } else {
                float* Crow = C + (size_t)gm * ldc + cOffE;
#pragma unroll
                for (int nj = 0; nj < 8; nj++) {
                    int gn0 = bn + warp_n * 64 + nj * 8 + tr * 2;
                    float v0 = acc[mi][nj][half * 2];
                    float v1 = acc[mi][nj][half * 2 + 1];
                    if (accumulate) {
                        v0 += Crow[(size_t)gn0 * 3];
                        v1 += Crow[(size_t)(gn0 + 1) * 3];
                    }
                    Crow[(size_t)gn0 * 3] = v0;
                    Crow[(size_t)(gn0 + 1) * 3] = v1;
                }
            }
        }
    }
}

// ---------------------------------------------------------------------------
// Gate: (N,1536) -> (N,1280)
// ---------------------------------------------------------------------------
__global__ void gate_kernel(const float* __restrict__ pre, float* __restrict__ out, int M)
{
    size_t idx = (size_t)blockIdx.x * blockDim.x + threadIdx.x;
    size_t total = (size_t)M * 1280;
    if (idx >= total) return;
    int c = (int)(idx % 1280);
    size_t r = idx / 1280;
    const float* prow = pre + r * 1536;
    float v;
    if (c < 512) {
        float s = prow[c];
        v = s / (1.f + __expf(-s));
    } else {
        int c2 = c - 512;
        int o = c2 / 3;
        float g = 1.f / (1.f + __expf(-prow[512 + o]));
        v = prow[768 + c2] * g;
    }
    out[idx] = v;
}

// ---------------------------------------------------------------------------
// Batch-norm (deterministic two-stage reduction)
// ---------------------------------------------------------------------------
__global__ void bn_partial_kernel(const float* __restrict__ out,
                                  float* __restrict__ psum, float* __restrict__ psq, int M)
{
    int c = threadIdx.x;
    float s = 0.f, sq = 0.f;
    for (int r = blockIdx.x; r < M; r += gridDim.x) {
        float x = out[(size_t)r * 640 + c];
        s += x; sq += x * x;
    }
    psq[blockIdx.x * 640 + c] = sq;
    if (c < 256) psum[blockIdx.x * 256 + c] = s;
}

__global__ void bn_final_kernel(const float* __restrict__ psum, const float* __restrict__ psq,
                                const float* __restrict__ w, const float* __restrict__ b,
                                float* __restrict__ scale, float* __restrict__ shift, int M)
{
    __shared__ float ssq[640];
    __shared__ float ssum[256];
    int c = threadIdx.x;
    float sq = 0.f;
    for (int p = 0; p < NPART; p++) sq += psq[p * 640 + c];
    ssq[c] = sq;
    if (c < 256) {
        float s = 0.f;
        for (int p = 0; p < NPART; p++) s += psum[p * 256 + c];
        ssum[c] = s;
    }
    __syncthreads();
    float invN = 1.f / (float)M;
    if (c < 256) {
        float m = ssum[c] * invN;
        float var = ssq[c] * invN - m * m;
        float inv = rsqrtf(var + 1e-5f);
        float sc = inv * w[c];
        scale[c] = sc;
        shift[c] = b[c] - m * sc;
    } else if (c < 256 + 128) {
        int ch = c - 256;
        float t = ssq[256 + 3 * ch] + ssq[256 + 3 * ch + 1] + ssq[256 + 3 * ch + 2];
        float mean = t * invN * (1.f / 3.f);
        float inv = rsqrtf(mean + 1e-5f);
        float sc = inv * w[256 + ch];
#pragma unroll
        for (int d2 = 0; d2 < 3; d2++) {
            scale[256 + 3 * ch + d2] = sc;
            shift[256 + 3 * ch + d2] = 0.f;
        }
    }
}

__global__ void bn_apply_kernel(float* __restrict__ out,
                                const float* __restrict__ scale,
                                const float* __restrict__ shift, int M)
{
    size_t idx = (size_t)blockIdx.x * blockDim.x + threadIdx.x;
    size_t total = (size_t)M * 640;
    if (idx >= total) return;
    int c = (int)(idx % 640);
    out[idx] = out[idx] * __ldg(&scale[c]) + __ldg(&shift[c]);
}

// ---------------------------------------------------------------------------
extern "C" void kernel_launch(void* const* d_in, const int* in_sizes, int n_in,
                              void* d_out, int out_size)
{
    const float* features = (const float*)d_in[0];
    const float* W10 = (const float*)d_in[1];   // (256, 768)
    const float* W11 = (const float*)d_in[2];   // (128, 256)
    const float* W20 = (const float*)d_in[3];   // (512, 768)
    const float* W21 = (const float*)d_in[4];   // (256, 256)
    const float* W30 = (const float*)d_in[5];   // (512, 256)
    const float* W31 = (const float*)d_in[6];   // (256, 128)
    const float* B0  = (const float*)d_in[7];   // (256, 256)
    const float* B1  = (const float*)d_in[8];   // (128, 128)
    const float* bw  = (const float*)d_in[9];
    const float* bb  = (const float*)d_in[10];
    float* out = (float*)d_out;

    float *pre, *h, *psum, *psq, *sc, *sh;
    __nv_bfloat16* wb;
    cudaGetSymbolAddress((void**)&pre, g_pre);
    cudaGetSymbolAddress((void**)&h, g_h);
    cudaGetSymbolAddress((void**)&psum, g_psum);
    cudaGetSymbolAddress((void**)&psq, g_psq);
    cudaGetSymbolAddress((void**)&sc, g_scale);
    cudaGetSymbolAddress((void**)&sh, g_shift);
    cudaGetSymbolAddress((void**)&wb, g_wbuf);

    const int M = MROWS;
    const float s256 = 0.0625f;
    const float s128 = 0.08838834764831845f;
    const float s512 = 0.04419417382415922f;

    const int o10 = 0, o11 = 196608, o20 = 229376, o21 = 622592;
    const int o30 = 688128, o31 = 819200, ob0 = 851968, ob1 = 917504;
    __nv_bfloat16* lo = wb + WTOT;

    // ---- preconvert weights ----
    {
        struct { const float* W; int K, N, off; float s; } cw[8] = {
            {W10, 256, 768, o10, s256}, {W11, 128, 256, o11, s128},
            {W20, 512, 768, o20, s512}, {W21, 256, 256, o21, s256},
            {W30, 512, 256, o30, s512}, {W31, 256, 128, o31, s256},
            {B0,  256, 256, ob0, s256}, {B1,  128, 128, ob1, s128}};
        for (int i = 0; i < 8; i++) {
            int tot = cw[i].K * cw[i].N;
            conv_w_kernel<<<(tot + 255) / 256, 256>>>(cw[i].W, cw[i].K, cw[i].N, cw[i].s,
                                                      wb + cw[i].off, lo + cw[i].off);
        }
    }

    const int gy = (M + 127) / 128;   // 782
    cudaFuncSetAttribute(tc_gemm, cudaFuncAttributeMaxDynamicSharedMemorySize, SMEM_BYTES);

    // ---- layer 1 ----
    tc_gemm<<<dim3(6, gy, 1), 256, SMEM_BYTES>>>(features, 640, 0, 1, wb + o10, lo + o10,
                                                 pre, 1536, 0, 1, M, 256, 0);
    tc_gemm<<<dim3(2, gy, 3), 256, SMEM_BYTES>>>(features, 640, 256, 3, wb + o11, lo + o11,
                                                 pre, 1536, 768, 3, M, 128, 0);
    {
        size_t total = (size_t)M * 1280;
        gate_kernel<<<(unsigned)((total + 255) / 256), 256>>>(pre, h, M);
    }
    // ---- layer 2 ----
    tc_gemm<<<dim3(6, gy, 1), 256, SMEM_BYTES>>>(h, 1280, 0, 1, wb + o20, lo + o20,
                                                 pre, 1536, 0, 1, M, 512, 0);
    tc_gemm<<<dim3(2, gy, 3), 256, SMEM_BYTES>>>(h, 1280, 512, 3, wb + o21, lo + o21,
                                                 pre, 1536, 768, 3, M, 256, 0);
    {
        size_t total = (size_t)M * 1280;
        gate_kernel<<<(unsigned)((total + 255) / 256), 256>>>(pre, h, M);
    }
    // ---- layer 3 + bypass ----
    tc_gemm<<<dim3(2, gy, 1), 256, SMEM_BYTES>>>(h, 1280, 0, 1, wb + o30, lo + o30,
                                                 out, 640, 0, 1, M, 512, 0);
    tc_gemm<<<dim3(1, gy, 3), 256, SMEM_BYTES>>>(h, 1280, 512, 3, wb + o31, lo + o31,
                                                 out, 640, 256, 3, M, 256, 0);
    tc_gemm<<<dim3(2, gy, 1), 256, SMEM_BYTES>>>(features, 640, 0, 1, wb + ob0, lo + ob0,
                                                 out, 640, 0, 1, M, 256, 1);
    tc_gemm<<<dim3(1, gy, 3), 256, SMEM_BYTES>>>(features, 640, 256, 3, wb + ob1, lo + ob1,
                                                 out, 640, 256, 3, M, 128, 1);

    // ---- batch norm ----
    bn_partial_kernel<<<NPART, 640>>>(out, psum, psq, M);
    bn_final_kernel<<<1, 640>>>(psum, psq, bw, bb, sc, sh, M);
    {
        size_t total = (size_t)M * 640;
        bn_apply_kernel<<<(unsigned)((total + 255) / 256), 256>>>(out, sc, sh, M);
    }
}